// round 1
// baseline (speedup 1.0000x reference)
#include <cuda_runtime.h>

#define NN 100000
#define NE 1600000
#define DD 128

// ---------------- scratch (device globals; no allocations allowed) ----------
__device__ float g_bufA[(size_t)NN * DD];   // h0, then agg
__device__ float g_bufB[(size_t)NN * DD];   // h
__device__ float g_colsum[DD];
__device__ float g_colsq[DD];
__device__ float g_bnscale[DD];
__device__ float g_bnshift[DD];
__device__ int   g_outdeg[NN];
__device__ int   g_indeg[NN];
__device__ float g_nsrc[NN];
__device__ float g_ndst[NN];
__device__ int   g_rowptr[NN + 1];
__device__ int   g_cursor[NN];
__device__ int   g_csrsrc[NE];
__device__ int   g_bsums[128];

// ---------------- init ------------------------------------------------------
__global__ void init_k() {
    int i = blockIdx.x * blockDim.x + threadIdx.x;
    if (i < DD) { g_colsum[i] = 0.f; g_colsq[i] = 0.f; }
    if (i < NN) { g_outdeg[i] = 0; g_indeg[i] = 0; }
}

// ---------------- degrees / norms ------------------------------------------
__global__ void degree_k(const int* __restrict__ src, const int* __restrict__ dst) {
    int i = blockIdx.x * blockDim.x + threadIdx.x;
    if (i < NE) {
        atomicAdd(&g_outdeg[src[i]], 1);
        atomicAdd(&g_indeg[dst[i]], 1);
    }
}

__global__ void norm_k() {
    int i = blockIdx.x * blockDim.x + threadIdx.x;
    if (i < NN) {
        g_nsrc[i] = rsqrtf((float)max(g_outdeg[i], 1));
        g_ndst[i] = rsqrtf((float)max(g_indeg[i], 1));
    }
}

// ---------------- CSR build (exclusive scan over in-degree) -----------------
__global__ void scanA_k() {
    __shared__ int sdata[1024];
    int t = threadIdx.x;
    int i = blockIdx.x * 1024 + t;
    int x = (i < NN) ? g_indeg[i] : 0;
    sdata[t] = x;
    __syncthreads();
    for (int off = 1; off < 1024; off <<= 1) {
        int v = (t >= off) ? sdata[t - off] : 0;
        __syncthreads();
        sdata[t] += v;
        __syncthreads();
    }
    if (i < NN) g_rowptr[i] = sdata[t] - x;   // exclusive
    if (t == 1023) g_bsums[blockIdx.x] = sdata[1023];
}

__global__ void scanB_k(int nblocks) {
    if (threadIdx.x == 0) {
        int run = 0;
        for (int j = 0; j < nblocks; j++) {
            int v = g_bsums[j];
            g_bsums[j] = run;
            run += v;
        }
    }
}

__global__ void scanC_k() {
    int i = blockIdx.x * blockDim.x + threadIdx.x;
    if (i < NN) {
        int v = g_rowptr[i] + g_bsums[i >> 10];
        g_rowptr[i] = v;
        g_cursor[i] = v;
    }
    if (i == 0) g_rowptr[NN] = NE;
}

__global__ void csrfill_k(const int* __restrict__ src, const int* __restrict__ dst) {
    int i = blockIdx.x * blockDim.x + threadIdx.x;
    if (i < NE) {
        int pos = atomicAdd(&g_cursor[dst[i]], 1);
        g_csrsrc[pos] = src[i];
    }
}

// ---------------- GEMM: C[M,128] = f(A)[M,128] @ W[128,128] epilogue --------
// MODE 0: C = A@W + bias; accumulate column sum/sumsq into g_colsum/g_colsq
// MODE 1: C = relu(bn(A))@W + bias   (bn via g_bnscale/g_bnshift, fused on load)
// MODE 2: C = (A@W) * g_ndst[row] + bias
// selA/selC: 0 -> g_bufA, 1 -> g_bufB, 2 -> external pointer
template <int MODE>
__global__ void gemm_k(const float* __restrict__ Aext, int selA,
                       const float* __restrict__ W,
                       const float* __restrict__ bias,
                       float* __restrict__ Cext, int selC)
{
    extern __shared__ float smem[];
    float* sW = smem;             // 128*128
    float* sA = smem + DD * DD;   // 64*128

    const float* A = (selA == 0) ? g_bufA : (selA == 1) ? g_bufB : Aext;
    float*       C = (selC == 0) ? g_bufA : (selC == 1) ? g_bufB : Cext;

    int tid = threadIdx.x;
    int tx = tid & 31;
    int ty = tid >> 5;
    int rowBase = blockIdx.x * 64;

    // stage W (16384 floats)
    {
        const float4* W4 = (const float4*)W;
        float4* sW4 = (float4*)sW;
#pragma unroll
        for (int i = 0; i < 16; i++) sW4[tid + i * 256] = W4[tid + i * 256];
    }

    // stage A tile (64 x 128), optionally BN+ReLU transformed
    {
        float4* sA4 = (float4*)sA;
#pragma unroll
        for (int i = 0; i < 8; i++) {
            int t = tid + i * 256;              // 0..2047 float4 slots
            int r = t >> 5, c4 = t & 31;
            int gr = rowBase + r;
            float4 v = make_float4(0.f, 0.f, 0.f, 0.f);
            if (gr < NN) v = ((const float4*)A)[(size_t)gr * 32 + c4];
            if (MODE == 1) {
                float4 sc = ((const float4*)g_bnscale)[c4];
                float4 sh = ((const float4*)g_bnshift)[c4];
                v.x = fmaxf(fmaf(v.x, sc.x, sh.x), 0.f);
                v.y = fmaxf(fmaf(v.y, sc.y, sh.y), 0.f);
                v.z = fmaxf(fmaf(v.z, sc.z, sh.z), 0.f);
                v.w = fmaxf(fmaf(v.w, sc.w, sh.w), 0.f);
            }
            sA4[t] = v;
        }
    }
    __syncthreads();

    float acc[8][4];
#pragma unroll
    for (int i = 0; i < 8; i++)
#pragma unroll
        for (int j = 0; j < 4; j++) acc[i][j] = 0.f;

    const float4* sWf4 = (const float4*)sW;
#pragma unroll 4
    for (int k = 0; k < DD; k++) {
        float4 b = sWf4[k * 32 + tx];
#pragma unroll
        for (int i = 0; i < 8; i++) {
            float a = sA[(ty * 8 + i) * DD + k];   // warp-uniform broadcast
            acc[i][0] = fmaf(a, b.x, acc[i][0]);
            acc[i][1] = fmaf(a, b.y, acc[i][1]);
            acc[i][2] = fmaf(a, b.z, acc[i][2]);
            acc[i][3] = fmaf(a, b.w, acc[i][3]);
        }
    }

    float4 bs = ((const float4*)bias)[tx];
    float psum[4] = {0.f, 0.f, 0.f, 0.f};
    float psq[4]  = {0.f, 0.f, 0.f, 0.f};

#pragma unroll
    for (int i = 0; i < 8; i++) {
        int gr = rowBase + ty * 8 + i;
        if (gr < NN) {
            float4 v;
            if (MODE == 2) {
                float ns = g_ndst[gr];
                v.x = fmaf(acc[i][0], ns, bs.x);
                v.y = fmaf(acc[i][1], ns, bs.y);
                v.z = fmaf(acc[i][2], ns, bs.z);
                v.w = fmaf(acc[i][3], ns, bs.w);
            } else {
                v.x = acc[i][0] + bs.x;
                v.y = acc[i][1] + bs.y;
                v.z = acc[i][2] + bs.z;
                v.w = acc[i][3] + bs.w;
            }
            ((float4*)C)[(size_t)gr * 32 + tx] = v;
            if (MODE == 0) {
                psum[0] += v.x; psum[1] += v.y; psum[2] += v.z; psum[3] += v.w;
                psq[0] += v.x * v.x; psq[1] += v.y * v.y;
                psq[2] += v.z * v.z; psq[3] += v.w * v.w;
            }
        }
    }

    if (MODE == 0) {
        __syncthreads();            // done with sA, reuse for reduction
        float* r0 = sA;             // 8 x 128
        float* r1 = sA + 1024;      // 8 x 128
#pragma unroll
        for (int j = 0; j < 4; j++) {
            r0[ty * DD + tx * 4 + j] = psum[j];
            r1[ty * DD + tx * 4 + j] = psq[j];
        }
        __syncthreads();
        if (tid < DD) {
            float s = 0.f, q = 0.f;
#pragma unroll
            for (int w = 0; w < 8; w++) {
                s += r0[w * DD + tid];
                q += r1[w * DD + tid];
            }
            atomicAdd(&g_colsum[tid], s);
            atomicAdd(&g_colsq[tid], q);
        }
    }
}

// ---------------- BN finalize ----------------------------------------------
__global__ void bn_finalize_k(const float* __restrict__ gamma, const float* __restrict__ beta) {
    int c = threadIdx.x;
    if (c < DD) {
        float inv_n = 1.f / (float)NN;
        float mean = g_colsum[c] * inv_n;
        float var = g_colsq[c] * inv_n - mean * mean;
        float rs = rsqrtf(var + 1e-5f);
        float g = gamma[c] * rs;
        g_bnscale[c] = g;
        g_bnshift[c] = beta[c] - mean * g;
    }
}

// ---------------- pull-side edge gather ------------------------------------
// agg[v] = sum_{e : dst(e)=v} relu(h[src(e)]) * nsrc[src(e)]
// One warp per node; float4 per lane. Reads g_bufB, writes g_bufA.
__global__ void gather_k() {
    int node = blockIdx.x * 8 + (threadIdx.x >> 5);
    if (node >= NN) return;
    int lane = threadIdx.x & 31;
    int e = g_rowptr[node];
    int end = g_rowptr[node + 1];
    float4 acc = make_float4(0.f, 0.f, 0.f, 0.f);
    const float4* h4 = (const float4*)g_bufB;
    for (; e < end; e++) {
        int s = g_csrsrc[e];          // warp-uniform
        float ns = g_nsrc[s];         // warp-uniform
        float4 v = h4[(size_t)s * 32 + lane];
        acc.x = fmaf(fmaxf(v.x, 0.f), ns, acc.x);
        acc.y = fmaf(fmaxf(v.y, 0.f), ns, acc.y);
        acc.z = fmaf(fmaxf(v.z, 0.f), ns, acc.z);
        acc.w = fmaf(fmaxf(v.w, 0.f), ns, acc.w);
    }
    ((float4*)g_bufA)[(size_t)node * 32 + lane] = acc;
}

// ---------------- launch ----------------------------------------------------
extern "C" void kernel_launch(void* const* d_in, const int* in_sizes, int n_in,
                              void* d_out, int out_size)
{
    const float* in_feat = (const float*)d_in[0];
    const int*   src     = (const int*)d_in[1];
    const int*   dst     = (const int*)d_in[2];
    const float* W1      = (const float*)d_in[3];
    const float* b1      = (const float*)d_in[4];
    const float* gamma   = (const float*)d_in[5];
    const float* beta    = (const float*)d_in[6];
    const float* W2      = (const float*)d_in[7];
    const float* b2      = (const float*)d_in[8];
    const float* Wc      = (const float*)d_in[9];
    const float* bc      = (const float*)d_in[10];
    float* out = (float*)d_out;

    const int smem = (DD * DD + 64 * DD) * (int)sizeof(float);   // 98304 B
    cudaFuncSetAttribute(gemm_k<0>, cudaFuncAttributeMaxDynamicSharedMemorySize, smem);
    cudaFuncSetAttribute(gemm_k<1>, cudaFuncAttributeMaxDynamicSharedMemorySize, smem);
    cudaFuncSetAttribute(gemm_k<2>, cudaFuncAttributeMaxDynamicSharedMemorySize, smem);

    const int nbRows = (NN + 63) / 64;          // 1563
    const int nbN    = (NN + 255) / 256;
    const int nbE    = (NE + 255) / 256;
    const int nbScan = (NN + 1023) / 1024;      // 98

    init_k<<<nbN, 256>>>();

    // graph structure (independent of MLP)
    degree_k<<<nbE, 256>>>(src, dst);
    norm_k<<<nbN, 256>>>();
    scanA_k<<<nbScan, 1024>>>();
    scanB_k<<<1, 32>>>(nbScan);
    scanC_k<<<nbN, 256>>>();
    csrfill_k<<<nbE, 256>>>(src, dst);

    // MLP: h0 = X@W1+b1 (+stats) ; h = relu(bn(h0))@W2+b2
    gemm_k<0><<<nbRows, 256, smem>>>(in_feat, 2, W1, b1, nullptr, 0);   // -> g_bufA
    bn_finalize_k<<<1, 128>>>(gamma, beta);
    gemm_k<1><<<nbRows, 256, smem>>>(nullptr, 0, W2, b2, nullptr, 1);   // A=g_bufA -> g_bufB

    // 3 propagation steps: gather(g_bufB -> g_bufA); h = (agg@Wc)*ndst + bc
    for (int step = 0; step < 3; step++) {
        gather_k<<<NN / 8, 256>>>();
        if (step < 2)
            gemm_k<2><<<nbRows, 256, smem>>>(nullptr, 0, Wc, bc, nullptr, 1);  // -> g_bufB
        else
            gemm_k<2><<<nbRows, 256, smem>>>(nullptr, 0, Wc, bc, out, 2);      // -> d_out
    }
}

// round 3
// speedup vs baseline: 1.2555x; 1.2555x over previous
#include <cuda_runtime.h>
#include <cuda_bf16.h>
#include <cstdint>

#define NN 100000
#define NE 1600000
#define DD 128

// ======================= helpers ============================================
__device__ __forceinline__ uint32_t smem_to_u32(const void* p) {
    uint32_t a;
    asm("{ .reg .u64 t; cvta.to.shared.u64 t, %1; cvt.u32.u64 %0, t; }" : "=r"(a) : "l"(p));
    return a;
}

__device__ __forceinline__ void ldsm_x4(uint32_t& r0, uint32_t& r1, uint32_t& r2, uint32_t& r3,
                                        uint32_t addr) {
    asm volatile("ldmatrix.sync.aligned.m8n8.x4.shared.b16 {%0,%1,%2,%3}, [%4];"
                 : "=r"(r0), "=r"(r1), "=r"(r2), "=r"(r3) : "r"(addr));
}
__device__ __forceinline__ void ldsm_x2(uint32_t& r0, uint32_t& r1, uint32_t addr) {
    asm volatile("ldmatrix.sync.aligned.m8n8.x2.shared.b16 {%0,%1}, [%2];"
                 : "=r"(r0), "=r"(r1) : "r"(addr));
}
__device__ __forceinline__ void mma16816(float* c, uint32_t a0, uint32_t a1, uint32_t a2,
                                         uint32_t a3, uint32_t b0, uint32_t b1) {
    asm volatile("mma.sync.aligned.m16n8k16.row.col.f32.bf16.bf16.f32 "
                 "{%0,%1,%2,%3}, {%4,%5,%6,%7}, {%8,%9}, {%0,%1,%2,%3};"
                 : "+f"(c[0]), "+f"(c[1]), "+f"(c[2]), "+f"(c[3])
                 : "r"(a0), "r"(a1), "r"(a2), "r"(a3), "r"(b0), "r"(b1));
}

// swizzled byte offset of bf16 element (r, c) in a 128x128 tile (row = 256 B)
__device__ __host__ __forceinline__ uint32_t sw_off(int r, int c) {
    int c2 = c >> 3;                       // 16B chunk index 0..15
    int sw = (c2 & 8) | ((c2 ^ r) & 7);    // XOR low 3 bits with row
    return (uint32_t)(r * 256 + (sw << 4) + (c & 7) * 2);
}

// ======================= scratch (device globals) ===========================
__device__ float g_bufA[(size_t)NN * DD];   // h0, then agg
__device__ float g_bufB[(size_t)NN * DD];   // h
__device__ float g_colsum[DD];
__device__ float g_colsq[DD];
__device__ float g_bnscale[DD];
__device__ float g_bnshift[DD];
__device__ int   g_outdeg[NN];
__device__ int   g_indeg[NN];
__device__ float g_nsrc[NN];
__device__ float g_ndst[NN];
__device__ int   g_rowptr[NN + 1];
__device__ int   g_cursor[NN];
__device__ int   g_csrsrc[NE];
__device__ int   g_bsums[128];
// pre-transposed + split + swizzled weight images (Wt[n][k], smem layout image)
__device__ __align__(16) __nv_bfloat16 g_Whi[3][16384];
__device__ __align__(16) __nv_bfloat16 g_Wlo[3][16384];

// ======================= init / degrees / norms =============================
__global__ void init_k() {
    int i = blockIdx.x * blockDim.x + threadIdx.x;
    if (i < DD) { g_colsum[i] = 0.f; g_colsq[i] = 0.f; }
    if (i < NN) { g_outdeg[i] = 0; g_indeg[i] = 0; }
}

__global__ void degree_k(const int* __restrict__ src, const int* __restrict__ dst) {
    int i = blockIdx.x * blockDim.x + threadIdx.x;
    if (i < NE) {
        atomicAdd(&g_outdeg[src[i]], 1);
        atomicAdd(&g_indeg[dst[i]], 1);
    }
}

__global__ void norm_k() {
    int i = blockIdx.x * blockDim.x + threadIdx.x;
    if (i < NN) {
        g_nsrc[i] = rsqrtf((float)max(g_outdeg[i], 1));
        g_ndst[i] = rsqrtf((float)max(g_indeg[i], 1));
    }
}

// ======================= CSR build ==========================================
__global__ void scanA_k() {
    __shared__ int sdata[1024];
    int t = threadIdx.x;
    int i = blockIdx.x * 1024 + t;
    int x = (i < NN) ? g_indeg[i] : 0;
    sdata[t] = x;
    __syncthreads();
    for (int off = 1; off < 1024; off <<= 1) {
        int v = (t >= off) ? sdata[t - off] : 0;
        __syncthreads();
        sdata[t] += v;
        __syncthreads();
    }
    if (i < NN) g_rowptr[i] = sdata[t] - x;
    if (t == 1023) g_bsums[blockIdx.x] = sdata[1023];
}

__global__ void scanB_k(int nblocks) {
    if (threadIdx.x == 0) {
        int run = 0;
        for (int j = 0; j < nblocks; j++) { int v = g_bsums[j]; g_bsums[j] = run; run += v; }
    }
}

__global__ void scanC_k() {
    int i = blockIdx.x * blockDim.x + threadIdx.x;
    if (i < NN) {
        int v = g_rowptr[i] + g_bsums[i >> 10];
        g_rowptr[i] = v;
        g_cursor[i] = v;
    }
    if (i == 0) g_rowptr[NN] = NE;
}

__global__ void csrfill_k(const int* __restrict__ src, const int* __restrict__ dst) {
    int i = blockIdx.x * blockDim.x + threadIdx.x;
    if (i < NE) {
        int pos = atomicAdd(&g_cursor[dst[i]], 1);
        g_csrsrc[pos] = src[i];
    }
}

// ======================= weight prep ========================================
// Wt[n][k] = W[k][n], split into bf16 hi/lo, stored at swizzled offsets.
__global__ void prep_w(const float* __restrict__ W, int slot) {
    int idx = blockIdx.x * 256 + threadIdx.x;   // 0..16383
    int n = idx >> 7, k = idx & 127;
    float w = W[k * DD + n];
    __nv_bfloat16 hi = __float2bfloat16(w);
    float r = w - __bfloat162float(hi);
    __nv_bfloat16 lo = __float2bfloat16(r);
    uint32_t o = sw_off(n, k) >> 1;
    g_Whi[slot][o] = hi;
    g_Wlo[slot][o] = lo;
}

// ======================= column stats for BN ================================
__global__ void colstats_k() {
    __shared__ float rs[8][DD];
    __shared__ float rq[8][DD];
    int tid = threadIdx.x;
    int c4 = tid & 31;
    int g = tid >> 5;
    float4 s = make_float4(0.f, 0.f, 0.f, 0.f);
    float4 q = make_float4(0.f, 0.f, 0.f, 0.f);
    const float4* A4 = (const float4*)g_bufA;
    for (int r = blockIdx.x * 8 + g; r < NN; r += gridDim.x * 8) {
        float4 v = A4[(size_t)r * 32 + c4];
        s.x += v.x; s.y += v.y; s.z += v.z; s.w += v.w;
        q.x += v.x * v.x; q.y += v.y * v.y; q.z += v.z * v.z; q.w += v.w * v.w;
    }
    rs[g][c4 * 4 + 0] = s.x; rs[g][c4 * 4 + 1] = s.y; rs[g][c4 * 4 + 2] = s.z; rs[g][c4 * 4 + 3] = s.w;
    rq[g][c4 * 4 + 0] = q.x; rq[g][c4 * 4 + 1] = q.y; rq[g][c4 * 4 + 2] = q.z; rq[g][c4 * 4 + 3] = q.w;
    __syncthreads();
    if (tid < DD) {
        float ss = 0.f, qq = 0.f;
#pragma unroll
        for (int w = 0; w < 8; w++) { ss += rs[w][tid]; qq += rq[w][tid]; }
        atomicAdd(&g_colsum[tid], ss);
        atomicAdd(&g_colsq[tid], qq);
    }
}

__global__ void bn_finalize_k(const float* __restrict__ gamma, const float* __restrict__ beta) {
    int c = threadIdx.x;
    if (c < DD) {
        float inv_n = 1.f / (float)NN;
        float mean = g_colsum[c] * inv_n;
        float var = g_colsq[c] * inv_n - mean * mean;
        float rs = rsqrtf(var + 1e-5f);
        float gsc = gamma[c] * rs;
        g_bnscale[c] = gsc;
        g_bnshift[c] = beta[c] - mean * gsc;
    }
}

// ======================= tensor-core GEMM (mma.sync bf16 split) =============
// C[tile 128, 128] = f(A) @ W via 3 passes: AhiBhi + AhiBlo + AloBhi.
// ALOAD: 0 plain, 1 BN+ReLU on load. EPI: 0 +bias, 1 *ndst+bias.
#define SM_BIAS  0
#define SM_AHI   1024
#define SM_ALO   33792
#define SM_BHI   66560
#define SM_BLO   99328
#define SM_TOTAL 132096

template <int ALOAD, int EPI>
__global__ void __launch_bounds__(256, 1)
gemm_mma(const float* __restrict__ Aext, int selA,
         int wslot,
         const float* __restrict__ bias,
         float* __restrict__ Cext, int selC)
{
    extern __shared__ char smem[];
    uint32_t sb = smem_to_u32(smem);
    int tid = threadIdx.x;
    int lane = tid & 31;
    int wid = tid >> 5;
    int rowBase = blockIdx.x * 128;

    const float* A = (selA == 0) ? g_bufA : (selA == 1) ? g_bufB : Aext;
    float*       C = (selC == 0) ? g_bufA : (selC == 1) ? g_bufB : Cext;

    // bias -> smem
    if (tid < 32) ((float4*)(smem + SM_BIAS))[tid] = ((const float4*)bias)[tid];

    // B images: straight copy (2 x 32 KB)
    {
        const uint4* bh = (const uint4*)g_Whi[wslot];
        const uint4* bl = (const uint4*)g_Wlo[wslot];
        uint4* sh = (uint4*)(smem + SM_BHI);
        uint4* sl = (uint4*)(smem + SM_BLO);
#pragma unroll
        for (int i = 0; i < 8; i++) {
            sh[tid + i * 256] = bh[tid + i * 256];
            sl[tid + i * 256] = bl[tid + i * 256];
        }
    }

    // A tile: fp32 load, optional BN+ReLU, split bf16 hi/lo, swizzled smem store
#pragma unroll
    for (int i = 0; i < 16; i++) {
        int t = tid + i * 256;        // 0..4095 float4 slots
        int r = t >> 5, q = t & 31;   // row, float4-col
        int gr = rowBase + r;
        float4 v = make_float4(0.f, 0.f, 0.f, 0.f);
        if (gr < NN) v = ((const float4*)A)[(size_t)gr * 32 + q];
        if (ALOAD == 1) {
            float4 sc = ((const float4*)g_bnscale)[q];
            float4 sh = ((const float4*)g_bnshift)[q];
            v.x = fmaxf(fmaf(v.x, sc.x, sh.x), 0.f);
            v.y = fmaxf(fmaf(v.y, sc.y, sh.y), 0.f);
            v.z = fmaxf(fmaf(v.z, sc.z, sh.z), 0.f);
            v.w = fmaxf(fmaf(v.w, sc.w, sh.w), 0.f);
        }
        __nv_bfloat162 h01 = __floats2bfloat162_rn(v.x, v.y);
        __nv_bfloat162 h23 = __floats2bfloat162_rn(v.z, v.w);
        float lx = v.x - __bfloat162float(__low2bfloat16(h01));
        float ly = v.y - __bfloat162float(__high2bfloat16(h01));
        float lz = v.z - __bfloat162float(__low2bfloat16(h23));
        float lw = v.w - __bfloat162float(__high2bfloat16(h23));
        __nv_bfloat162 l01 = __floats2bfloat162_rn(lx, ly);
        __nv_bfloat162 l23 = __floats2bfloat162_rn(lz, lw);
        uint32_t off = sw_off(r, q * 4);
        asm volatile("st.shared.v2.b32 [%0], {%1, %2};" :: "r"(sb + SM_AHI + off),
                     "r"(*(uint32_t*)&h01), "r"(*(uint32_t*)&h23) : "memory");
        asm volatile("st.shared.v2.b32 [%0], {%1, %2};" :: "r"(sb + SM_ALO + off),
                     "r"(*(uint32_t*)&l01), "r"(*(uint32_t*)&l23) : "memory");
    }
    __syncthreads();

    // accumulators: 16 n-blocks of 8 cols, 16 rows per warp
    float acc[16][4];
#pragma unroll
    for (int nb = 0; nb < 16; nb++)
#pragma unroll
        for (int j = 0; j < 4; j++) acc[nb][j] = 0.f;

#pragma unroll
    for (int pass = 0; pass < 3; pass++) {
        uint32_t aBase = sb + ((pass == 2) ? SM_ALO : SM_AHI);
        uint32_t bBase = sb + ((pass == 1) ? SM_BLO : SM_BHI);

        // cache A fragments for all 8 K-steps
        uint32_t af[8][4];
        int ar = wid * 16 + (lane & 15);
        int ah = lane >> 4;                         // k-chunk half (0/1)
#pragma unroll
        for (int ks = 0; ks < 8; ks++) {
            int c2 = ks * 2 + ah;
            int sw = (c2 & 8) | ((c2 ^ ar) & 7);
            uint32_t addr = aBase + ar * 256 + (sw << 4);
            ldsm_x4(af[ks][0], af[ks][1], af[ks][2], af[ks][3], addr);
        }

        int bn = (lane & 7);
        int bh = (lane >> 3) & 1;
#pragma unroll
        for (int nb = 0; nb < 16; nb++) {
            int brow = nb * 8 + bn;
#pragma unroll
            for (int ks = 0; ks < 8; ks++) {
                int c2 = ks * 2 + bh;
                int sw = (c2 & 8) | ((c2 ^ brow) & 7);
                uint32_t baddr = bBase + brow * 256 + (sw << 4);
                uint32_t b0, b1;
                ldsm_x2(b0, b1, baddr);
                mma16816(acc[nb], af[ks][0], af[ks][1], af[ks][2], af[ks][3], b0, b1);
            }
        }
    }

    // epilogue: C fragment -> global (float2 per thread per nb per row-half)
    int r0 = rowBase + wid * 16 + (lane >> 2);
    int r1 = r0 + 8;
    float nd0 = 1.f, nd1 = 1.f;
    if (EPI == 1) {
        if (r0 < NN) nd0 = g_ndst[r0];
        if (r1 < NN) nd1 = g_ndst[r1];
    }
    const float* sbias = (const float*)(smem + SM_BIAS);
#pragma unroll
    for (int nb = 0; nb < 16; nb++) {
        int col = nb * 8 + (lane & 3) * 2;
        float bx = sbias[col], by = sbias[col + 1];
        float2 v0, v1;
        if (EPI == 1) {
            v0.x = fmaf(acc[nb][0], nd0, bx); v0.y = fmaf(acc[nb][1], nd0, by);
            v1.x = fmaf(acc[nb][2], nd1, bx); v1.y = fmaf(acc[nb][3], nd1, by);
        } else {
            v0.x = acc[nb][0] + bx; v0.y = acc[nb][1] + by;
            v1.x = acc[nb][2] + bx; v1.y = acc[nb][3] + by;
        }
        if (r0 < NN) ((float2*)C)[(size_t)r0 * 64 + (col >> 1)] = v0;
        if (r1 < NN) ((float2*)C)[(size_t)r1 * 64 + (col >> 1)] = v1;
    }
}

// ======================= pull-side edge gather ==============================
__global__ void gather_k() {
    int node = blockIdx.x * 8 + (threadIdx.x >> 5);
    if (node >= NN) return;
    int lane = threadIdx.x & 31;
    int e = g_rowptr[node];
    int end = g_rowptr[node + 1];
    float4 acc = make_float4(0.f, 0.f, 0.f, 0.f);
    const float4* h4 = (const float4*)g_bufB;
    for (; e < end; e++) {
        int s = g_csrsrc[e];
        float ns = g_nsrc[s];
        float4 v = h4[(size_t)s * 32 + lane];
        acc.x = fmaf(fmaxf(v.x, 0.f), ns, acc.x);
        acc.y = fmaf(fmaxf(v.y, 0.f), ns, acc.y);
        acc.z = fmaf(fmaxf(v.z, 0.f), ns, acc.z);
        acc.w = fmaf(fmaxf(v.w, 0.f), ns, acc.w);
    }
    ((float4*)g_bufA)[(size_t)node * 32 + lane] = acc;
}

// ======================= launch =============================================
extern "C" void kernel_launch(void* const* d_in, const int* in_sizes, int n_in,
                              void* d_out, int out_size)
{
    const float* in_feat = (const float*)d_in[0];
    const int*   src     = (const int*)d_in[1];
    const int*   dst     = (const int*)d_in[2];
    const float* W1      = (const float*)d_in[3];
    const float* b1      = (const float*)d_in[4];
    const float* gamma   = (const float*)d_in[5];
    const float* beta    = (const float*)d_in[6];
    const float* W2      = (const float*)d_in[7];
    const float* b2      = (const float*)d_in[8];
    const float* Wc      = (const float*)d_in[9];
    const float* bc      = (const float*)d_in[10];
    float* out = (float*)d_out;

    cudaFuncSetAttribute(gemm_mma<0,0>, cudaFuncAttributeMaxDynamicSharedMemorySize, SM_TOTAL);
    cudaFuncSetAttribute(gemm_mma<1,0>, cudaFuncAttributeMaxDynamicSharedMemorySize, SM_TOTAL);
    cudaFuncSetAttribute(gemm_mma<0,1>, cudaFuncAttributeMaxDynamicSharedMemorySize, SM_TOTAL);

    const int nbTiles = (NN + 127) / 128;       // 782
    const int nbN     = (NN + 255) / 256;
    const int nbE     = (NE + 255) / 256;
    const int nbScan  = (NN + 1023) / 1024;     // 98

    init_k<<<nbN, 256>>>();

    // weight prep
    prep_w<<<64, 256>>>(W1, 0);
    prep_w<<<64, 256>>>(W2, 1);
    prep_w<<<64, 256>>>(Wc, 2);

    // graph structure
    degree_k<<<nbE, 256>>>(src, dst);
    norm_k<<<nbN, 256>>>();
    scanA_k<<<nbScan, 1024>>>();
    scanB_k<<<1, 32>>>(nbScan);
    scanC_k<<<nbN, 256>>>();
    csrfill_k<<<nbE, 256>>>(src, dst);

    // MLP
    gemm_mma<0,0><<<nbTiles, 256, SM_TOTAL>>>(in_feat, 2, 0, b1, nullptr, 0);  // -> g_bufA
    colstats_k<<<625, 256>>>();
    bn_finalize_k<<<1, 128>>>(gamma, beta);
    gemm_mma<1,0><<<nbTiles, 256, SM_TOTAL>>>(nullptr, 0, 1, b2, nullptr, 1);  // -> g_bufB

    // propagation x3
    for (int step = 0; step < 3; step++) {
        gather_k<<<NN / 8, 256>>>();
        if (step < 2)
            gemm_mma<0,1><<<nbTiles, 256, SM_TOTAL>>>(nullptr, 0, 2, bc, nullptr, 1);
        else
            gemm_mma<0,1><<<nbTiles, 256, SM_TOTAL>>>(nullptr, 0, 2, bc, out, 2);
    }
}

// round 7
// speedup vs baseline: 1.4521x; 1.1566x over previous
#include <cuda_runtime.h>
#include <cuda_bf16.h>
#include <cstdint>

#define NN 100000
#define NE 1600000
#define DD 128

// ======================= helpers ============================================
__device__ __forceinline__ uint32_t smem_to_u32(const void* p) {
    uint32_t a;
    asm("{ .reg .u64 t; cvta.to.shared.u64 t, %1; cvt.u32.u64 %0, t; }" : "=r"(a) : "l"(p));
    return a;
}
__device__ __forceinline__ void ldsm_x4(uint32_t& r0, uint32_t& r1, uint32_t& r2, uint32_t& r3,
                                        uint32_t addr) {
    asm volatile("ldmatrix.sync.aligned.m8n8.x4.shared.b16 {%0,%1,%2,%3}, [%4];"
                 : "=r"(r0), "=r"(r1), "=r"(r2), "=r"(r3) : "r"(addr));
}
__device__ __forceinline__ void mma16816(float* c, uint32_t a0, uint32_t a1, uint32_t a2,
                                         uint32_t a3, uint32_t b0, uint32_t b1) {
    asm volatile("mma.sync.aligned.m16n8k16.row.col.f32.bf16.bf16.f32 "
                 "{%0,%1,%2,%3}, {%4,%5,%6,%7}, {%8,%9}, {%0,%1,%2,%3};"
                 : "+f"(c[0]), "+f"(c[1]), "+f"(c[2]), "+f"(c[3])
                 : "r"(a0), "r"(a1), "r"(a2), "r"(a3), "r"(b0), "r"(b1));
}
// swizzled byte offset of bf16 element (r, c) in a 128x128 tile (row = 256 B)
__device__ __host__ __forceinline__ uint32_t sw_off(int r, int c) {
    int c2 = c >> 3;                       // 16B chunk index 0..15
    int sw = (c2 & 8) | ((c2 ^ r) & 7);    // XOR low 3 bits with row
    return (uint32_t)(r * 256 + (sw << 4) + (c & 7) * 2);
}

// ======================= scratch (device globals) ===========================
__device__ float g_bufA[(size_t)NN * DD];   // h0, then agg
__device__ float g_bufB[(size_t)NN * DD];   // h
__device__ float g_colsum[DD];
__device__ float g_colsq[DD];
__device__ float g_bnscale[DD];
__device__ float g_bnshift[DD];
__device__ int   g_outdeg[NN];
__device__ int   g_indeg[NN];
__device__ float g_nsrc[NN];
__device__ float g_ndst[NN];
__device__ int   g_rowptr[NN + 1];
__device__ int   g_cursor[NN];
__device__ int   g_csrsrc[NE];
__device__ int   g_bsums[128];
__device__ __align__(16) __nv_bfloat16 g_Whi[3][16384];
__device__ __align__(16) __nv_bfloat16 g_Wlo[3][16384];

// ======================= graph-side kernels =================================
__global__ void init_graph_k() {
    int i = blockIdx.x * blockDim.x + threadIdx.x;
    if (i < NN) { g_outdeg[i] = 0; g_indeg[i] = 0; }
}

__global__ void degree_k(const int* __restrict__ src, const int* __restrict__ dst) {
    int i = blockIdx.x * blockDim.x + threadIdx.x;
    if (i < NE) {
        atomicAdd(&g_outdeg[src[i]], 1);
        atomicAdd(&g_indeg[dst[i]], 1);
    }
}

// scan over indeg (exclusive per block) + fused norm computation
__global__ void scanA_k() {
    __shared__ int sdata[1024];
    int t = threadIdx.x;
    int i = blockIdx.x * 1024 + t;
    int x = (i < NN) ? g_indeg[i] : 0;
    if (i < NN) {
        g_nsrc[i] = rsqrtf((float)max(g_outdeg[i], 1));
        g_ndst[i] = rsqrtf((float)max(x, 1));
    }
    sdata[t] = x;
    __syncthreads();
    for (int off = 1; off < 1024; off <<= 1) {
        int v = (t >= off) ? sdata[t - off] : 0;
        __syncthreads();
        sdata[t] += v;
        __syncthreads();
    }
    if (i < NN) g_rowptr[i] = sdata[t] - x;
    if (t == 1023) g_bsums[blockIdx.x] = sdata[1023];
}

__global__ void scanB_k(int nblocks) {
    if (threadIdx.x == 0) {
        int run = 0;
        for (int j = 0; j < nblocks; j++) { int v = g_bsums[j]; g_bsums[j] = run; run += v; }
    }
}

__global__ void scanC_k() {
    int i = blockIdx.x * blockDim.x + threadIdx.x;
    if (i < NN) {
        int v = g_rowptr[i] + g_bsums[i >> 10];
        g_rowptr[i] = v;
        g_cursor[i] = v;
    }
    if (i == 0) g_rowptr[NN] = NE;
}

__global__ void csrfill_k(const int* __restrict__ src, const int* __restrict__ dst) {
    int i = blockIdx.x * blockDim.x + threadIdx.x;
    if (i < NE) {
        int pos = atomicAdd(&g_cursor[dst[i]], 1);
        g_csrsrc[pos] = src[i];
    }
}

// ======================= MLP-side small kernels =============================
__global__ void init_mlp_k() {
    int i = threadIdx.x;
    if (i < DD) { g_colsum[i] = 0.f; g_colsq[i] = 0.f; }
}

// all three weights in one launch: slot = blockIdx.x / 64
__global__ void prep_w_all(const float* __restrict__ W1, const float* __restrict__ W2,
                           const float* __restrict__ Wc) {
    int slot = blockIdx.x >> 6;
    const float* W = (slot == 0) ? W1 : (slot == 1) ? W2 : Wc;
    int idx = (blockIdx.x & 63) * 256 + threadIdx.x;   // 0..16383
    int n = idx >> 7, k = idx & 127;
    float w = W[k * DD + n];
    __nv_bfloat16 hi = __float2bfloat16(w);
    float r = w - __bfloat162float(hi);
    __nv_bfloat16 lo = __float2bfloat16(r);
    uint32_t o = sw_off(n, k) >> 1;
    g_Whi[slot][o] = hi;
    g_Wlo[slot][o] = lo;
}

__global__ void colstats_k() {
    __shared__ float rs[8][DD];
    __shared__ float rq[8][DD];
    int tid = threadIdx.x;
    int c4 = tid & 31;
    int g = tid >> 5;
    float4 s = make_float4(0.f, 0.f, 0.f, 0.f);
    float4 q = make_float4(0.f, 0.f, 0.f, 0.f);
    const float4* A4 = (const float4*)g_bufA;
    for (int r = blockIdx.x * 8 + g; r < NN; r += gridDim.x * 8) {
        float4 v = A4[(size_t)r * 32 + c4];
        s.x += v.x; s.y += v.y; s.z += v.z; s.w += v.w;
        q.x += v.x * v.x; q.y += v.y * v.y; q.z += v.z * v.z; q.w += v.w * v.w;
    }
    rs[g][c4 * 4 + 0] = s.x; rs[g][c4 * 4 + 1] = s.y; rs[g][c4 * 4 + 2] = s.z; rs[g][c4 * 4 + 3] = s.w;
    rq[g][c4 * 4 + 0] = q.x; rq[g][c4 * 4 + 1] = q.y; rq[g][c4 * 4 + 2] = q.z; rq[g][c4 * 4 + 3] = q.w;
    __syncthreads();
    if (tid < DD) {
        float ss = 0.f, qq = 0.f;
#pragma unroll
        for (int w = 0; w < 8; w++) { ss += rs[w][tid]; qq += rq[w][tid]; }
        atomicAdd(&g_colsum[tid], ss);
        atomicAdd(&g_colsq[tid], qq);
    }
}

__global__ void bn_finalize_k(const float* __restrict__ gamma, const float* __restrict__ beta) {
    int c = threadIdx.x;
    if (c < DD) {
        float inv_n = 1.f / (float)NN;
        float mean = g_colsum[c] * inv_n;
        float var = g_colsq[c] * inv_n - mean * mean;
        float rs = rsqrtf(var + 1e-5f);
        float gsc = gamma[c] * rs;
        g_bnscale[c] = gsc;
        g_bnshift[c] = beta[c] - mean * gsc;
    }
}

// ======================= tensor-core GEMM (restructured) ====================
// C[tile 128, 128] = f(A) @ W, split bf16: AhiBhi + AhiBlo + AloBhi, fp32 acc.
#define SM_BIAS  0
#define SM_AHI   1024
#define SM_ALO   33792
#define SM_BHI   66560
#define SM_BLO   99328
#define SM_TOTAL 132096

template <int ALOAD, int EPI>
__global__ void __launch_bounds__(256, 1)
gemm_mma(const float* __restrict__ Aext, int selA,
         int wslot,
         const float* __restrict__ bias,
         float* __restrict__ Cext, int selC)
{
    extern __shared__ char smem[];
    uint32_t sb = smem_to_u32(smem);
    int tid = threadIdx.x;
    int lane = tid & 31;
    int wid = tid >> 5;
    int rowBase = blockIdx.x * 128;

    const float* A = (selA == 0) ? g_bufA : (selA == 1) ? g_bufB : Aext;
    float*       C = (selC == 0) ? g_bufA : (selC == 1) ? g_bufB : Cext;

    if (tid < 32) ((float4*)(smem + SM_BIAS))[tid] = ((const float4*)bias)[tid];

    // B images: straight copy (2 x 32 KB)
    {
        const uint4* bh = (const uint4*)g_Whi[wslot];
        const uint4* bl = (const uint4*)g_Wlo[wslot];
        uint4* sh = (uint4*)(smem + SM_BHI);
        uint4* sl = (uint4*)(smem + SM_BLO);
#pragma unroll
        for (int i = 0; i < 8; i++) {
            sh[tid + i * 256] = bh[tid + i * 256];
            sl[tid + i * 256] = bl[tid + i * 256];
        }
    }

    // A tile: fp32 load, optional BN+ReLU, split bf16 hi/lo, swizzled smem store
#pragma unroll
    for (int i = 0; i < 16; i++) {
        int t = tid + i * 256;
        int r = t >> 5, q = t & 31;
        int gr = rowBase + r;
        float4 v = make_float4(0.f, 0.f, 0.f, 0.f);
        if (gr < NN) v = ((const float4*)A)[(size_t)gr * 32 + q];
        if (ALOAD == 1) {
            float4 sc = ((const float4*)g_bnscale)[q];
            float4 sh = ((const float4*)g_bnshift)[q];
            v.x = fmaxf(fmaf(v.x, sc.x, sh.x), 0.f);
            v.y = fmaxf(fmaf(v.y, sc.y, sh.y), 0.f);
            v.z = fmaxf(fmaf(v.z, sc.z, sh.z), 0.f);
            v.w = fmaxf(fmaf(v.w, sc.w, sh.w), 0.f);
        }
        __nv_bfloat162 h01 = __floats2bfloat162_rn(v.x, v.y);
        __nv_bfloat162 h23 = __floats2bfloat162_rn(v.z, v.w);
        float lx = v.x - __bfloat162float(__low2bfloat16(h01));
        float ly = v.y - __bfloat162float(__high2bfloat16(h01));
        float lz = v.z - __bfloat162float(__low2bfloat16(h23));
        float lw = v.w - __bfloat162float(__high2bfloat16(h23));
        __nv_bfloat162 l01 = __floats2bfloat162_rn(lx, ly);
        __nv_bfloat162 l23 = __floats2bfloat162_rn(lz, lw);
        uint32_t off = sw_off(r, q * 4);
        asm volatile("st.shared.v2.b32 [%0], {%1, %2};" :: "r"(sb + SM_AHI + off),
                     "r"(*(uint32_t*)&h01), "r"(*(uint32_t*)&h23) : "memory");
        asm volatile("st.shared.v2.b32 [%0], {%1, %2};" :: "r"(sb + SM_ALO + off),
                     "r"(*(uint32_t*)&l01), "r"(*(uint32_t*)&l23) : "memory");
    }
    __syncthreads();

    // ---- A fragments (hi and lo) cached for all 8 K-steps -------------------
    uint32_t ah[8][4], al[8][4];
    {
        int ar = wid * 16 + (lane & 15);
        int akh = lane >> 4;
#pragma unroll
        for (int ks = 0; ks < 8; ks++) {
            int c2 = ks * 2 + akh;
            int sw = (c2 & 8) | ((c2 ^ ar) & 7);
            uint32_t aoff = (uint32_t)(ar * 256 + (sw << 4));
            ldsm_x4(ah[ks][0], ah[ks][1], ah[ks][2], ah[ks][3], sb + SM_AHI + aoff);
            ldsm_x4(al[ks][0], al[ks][1], al[ks][2], al[ks][3], sb + SM_ALO + aoff);
        }
    }

    float acc[16][4];
#pragma unroll
    for (int nb = 0; nb < 16; nb++)
#pragma unroll
        for (int j = 0; j < 4; j++) acc[nb][j] = 0.f;

    // ---- B: dual ldsm_x4 loads Bhi frag (r0,r1) + Blo frag (r2,r3) ----------
    // lanes 0-7:  Bhi k-lo rows | 8-15: Bhi k-hi | 16-23: Blo k-lo | 24-31: Blo k-hi
    int bn = lane & 7;
    int bkh = (lane >> 3) & 1;
    uint32_t bRegion = sb + ((lane >> 4) ? SM_BLO : SM_BHI);

    // process nb in pairs with interleaved MMAs (two independent acc chains)
#pragma unroll
    for (int nbp = 0; nbp < 8; nbp++) {
        int nb0 = nbp * 2, nb1 = nbp * 2 + 1;
        int brow0 = nb0 * 8 + bn;
        int brow1 = nb1 * 8 + bn;
        uint32_t bf0[8][4], bf1[8][4];
#pragma unroll
        for (int ks = 0; ks < 8; ks++) {
            int c2 = ks * 2 + bkh;
            int sw0 = (c2 & 8) | ((c2 ^ brow0) & 7);
            int sw1 = (c2 & 8) | ((c2 ^ brow1) & 7);
            ldsm_x4(bf0[ks][0], bf0[ks][1], bf0[ks][2], bf0[ks][3],
                    bRegion + brow0 * 256 + (sw0 << 4));
            ldsm_x4(bf1[ks][0], bf1[ks][1], bf1[ks][2], bf1[ks][3],
                    bRegion + brow1 * 256 + (sw1 << 4));
        }
#pragma unroll
        for (int ks = 0; ks < 8; ks++) {
            mma16816(acc[nb0], ah[ks][0], ah[ks][1], ah[ks][2], ah[ks][3], bf0[ks][0], bf0[ks][1]);
            mma16816(acc[nb1], ah[ks][0], ah[ks][1], ah[ks][2], ah[ks][3], bf1[ks][0], bf1[ks][1]);
            mma16816(acc[nb0], ah[ks][0], ah[ks][1], ah[ks][2], ah[ks][3], bf0[ks][2], bf0[ks][3]);
            mma16816(acc[nb1], ah[ks][0], ah[ks][1], ah[ks][2], ah[ks][3], bf1[ks][2], bf1[ks][3]);
            mma16816(acc[nb0], al[ks][0], al[ks][1], al[ks][2], al[ks][3], bf0[ks][0], bf0[ks][1]);
            mma16816(acc[nb1], al[ks][0], al[ks][1], al[ks][2], al[ks][3], bf1[ks][0], bf1[ks][1]);
        }
    }

    // epilogue
    int r0 = rowBase + wid * 16 + (lane >> 2);
    int r1 = r0 + 8;
    float nd0 = 1.f, nd1 = 1.f;
    if (EPI == 1) {
        if (r0 < NN) nd0 = g_ndst[r0];
        if (r1 < NN) nd1 = g_ndst[r1];
    }
    const float* sbias = (const float*)(smem + SM_BIAS);
#pragma unroll
    for (int nb = 0; nb < 16; nb++) {
        int col = nb * 8 + (lane & 3) * 2;
        float bx = sbias[col], by = sbias[col + 1];
        float2 v0, v1;
        if (EPI == 1) {
            v0.x = fmaf(acc[nb][0], nd0, bx); v0.y = fmaf(acc[nb][1], nd0, by);
            v1.x = fmaf(acc[nb][2], nd1, bx); v1.y = fmaf(acc[nb][3], nd1, by);
        } else {
            v0.x = acc[nb][0] + bx; v0.y = acc[nb][1] + by;
            v1.x = acc[nb][2] + bx; v1.y = acc[nb][3] + by;
        }
        if (r0 < NN) ((float2*)C)[(size_t)r0 * 64 + (col >> 1)] = v0;
        if (r1 < NN) ((float2*)C)[(size_t)r1 * 64 + (col >> 1)] = v1;
    }
}

// ======================= pull-side edge gather ==============================
__global__ void gather_k() {
    int node = blockIdx.x * 8 + (threadIdx.x >> 5);
    if (node >= NN) return;
    int lane = threadIdx.x & 31;
    int e = g_rowptr[node];
    int end = g_rowptr[node + 1];
    float4 acc = make_float4(0.f, 0.f, 0.f, 0.f);
    const float4* h4 = (const float4*)g_bufB;
    for (; e < end; e++) {
        int s = g_csrsrc[e];
        float ns = g_nsrc[s];
        float4 v = h4[(size_t)s * 32 + lane];
        acc.x = fmaf(fmaxf(v.x, 0.f), ns, acc.x);
        acc.y = fmaf(fmaxf(v.y, 0.f), ns, acc.y);
        acc.z = fmaf(fmaxf(v.z, 0.f), ns, acc.z);
        acc.w = fmaf(fmaxf(v.w, 0.f), ns, acc.w);
    }
    ((float4*)g_bufA)[(size_t)node * 32 + lane] = acc;
}

// ======================= launch =============================================
extern "C" void kernel_launch(void* const* d_in, const int* in_sizes, int n_in,
                              void* d_out, int out_size)
{
    const float* in_feat = (const float*)d_in[0];
    const int*   src     = (const int*)d_in[1];
    const int*   dst     = (const int*)d_in[2];
    const float* W1      = (const float*)d_in[3];
    const float* b1      = (const float*)d_in[4];
    const float* gamma   = (const float*)d_in[5];
    const float* beta    = (const float*)d_in[6];
    const float* W2      = (const float*)d_in[7];
    const float* b2      = (const float*)d_in[8];
    const float* Wc      = (const float*)d_in[9];
    const float* bc      = (const float*)d_in[10];
    float* out = (float*)d_out;

    cudaFuncSetAttribute(gemm_mma<0,0>, cudaFuncAttributeMaxDynamicSharedMemorySize, SM_TOTAL);
    cudaFuncSetAttribute(gemm_mma<1,0>, cudaFuncAttributeMaxDynamicSharedMemorySize, SM_TOTAL);
    cudaFuncSetAttribute(gemm_mma<0,1>, cudaFuncAttributeMaxDynamicSharedMemorySize, SM_TOTAL);

    const int nbTiles = (NN + 127) / 128;       // 782
    const int nbN     = (NN + 255) / 256;
    const int nbE     = (NE + 255) / 256;
    const int nbScan  = (NN + 1023) / 1024;     // 98

    // ---- fork: graph-structure chain on side stream -------------------------
    cudaStream_t s2;
    cudaEvent_t evFork, evJoin;
    cudaStreamCreateWithFlags(&s2, cudaStreamNonBlocking);
    cudaEventCreateWithFlags(&evFork, cudaEventDisableTiming);
    cudaEventCreateWithFlags(&evJoin, cudaEventDisableTiming);

    cudaEventRecord(evFork, 0);
    cudaStreamWaitEvent(s2, evFork, 0);

    init_graph_k<<<nbN, 256, 0, s2>>>();
    degree_k<<<nbE, 256, 0, s2>>>(src, dst);
    scanA_k<<<nbScan, 1024, 0, s2>>>();          // fused norm computation
    scanB_k<<<1, 32, 0, s2>>>(nbScan);
    scanC_k<<<nbN, 256, 0, s2>>>();
    csrfill_k<<<nbE, 256, 0, s2>>>(src, dst);
    cudaEventRecord(evJoin, s2);

    // ---- main stream: MLP chain --------------------------------------------
    init_mlp_k<<<1, 128>>>();
    prep_w_all<<<192, 256>>>(W1, W2, Wc);
    gemm_mma<0,0><<<nbTiles, 256, SM_TOTAL>>>(in_feat, 2, 0, b1, nullptr, 0);  // -> g_bufA
    colstats_k<<<625, 256>>>();
    bn_finalize_k<<<1, 128>>>(gamma, beta);
    gemm_mma<1,0><<<nbTiles, 256, SM_TOTAL>>>(nullptr, 0, 1, b2, nullptr, 1);  // -> g_bufB

    // ---- join, then propagation x3 -----------------------------------------
    cudaStreamWaitEvent(0, evJoin, 0);
    for (int step = 0; step < 3; step++) {
        gather_k<<<NN / 8, 256>>>();
        if (step < 2)
            gemm_mma<0,1><<<nbTiles, 256, SM_TOTAL>>>(nullptr, 0, 2, bc, nullptr, 1);
        else
            gemm_mma<0,1><<<nbTiles, 256, SM_TOTAL>>>(nullptr, 0, 2, bc, out, 2);
    }

    cudaEventDestroy(evFork);
    cudaEventDestroy(evJoin);
    cudaStreamDestroy(s2);
}

// round 8
// speedup vs baseline: 1.6246x; 1.1188x over previous
#include <cuda_runtime.h>
#include <cuda_bf16.h>
#include <cuda_fp16.h>
#include <cstdint>

#define NN 100000
#define NE 1600000
#define DD 128

// ======================= helpers ============================================
__device__ __forceinline__ uint32_t smem_to_u32(const void* p) {
    uint32_t a;
    asm("{ .reg .u64 t; cvta.to.shared.u64 t, %1; cvt.u32.u64 %0, t; }" : "=r"(a) : "l"(p));
    return a;
}
__device__ __forceinline__ void ldsm_x4(uint32_t& r0, uint32_t& r1, uint32_t& r2, uint32_t& r3,
                                        uint32_t addr) {
    asm volatile("ldmatrix.sync.aligned.m8n8.x4.shared.b16 {%0,%1,%2,%3}, [%4];"
                 : "=r"(r0), "=r"(r1), "=r"(r2), "=r"(r3) : "r"(addr));
}
__device__ __forceinline__ void mma16816(float* c, uint32_t a0, uint32_t a1, uint32_t a2,
                                         uint32_t a3, uint32_t b0, uint32_t b1) {
    asm volatile("mma.sync.aligned.m16n8k16.row.col.f32.bf16.bf16.f32 "
                 "{%0,%1,%2,%3}, {%4,%5,%6,%7}, {%8,%9}, {%0,%1,%2,%3};"
                 : "+f"(c[0]), "+f"(c[1]), "+f"(c[2]), "+f"(c[3])
                 : "r"(a0), "r"(a1), "r"(a2), "r"(a3), "r"(b0), "r"(b1));
}
// swizzled byte offset of bf16 element (r, c) in a 128x128 tile (row = 256 B)
__device__ __host__ __forceinline__ uint32_t sw_off(int r, int c) {
    int c2 = c >> 3;
    int sw = (c2 & 8) | ((c2 ^ r) & 7);
    return (uint32_t)(r * 256 + (sw << 4) + (c & 7) * 2);
}

// ======================= scratch (device globals) ===========================
__device__ float  g_bufA[(size_t)NN * DD];   // h0, then agg
__device__ __half g_msg[(size_t)NN * DD];    // relu(h)*nsrc, fp16
__device__ float  g_colsum[DD];
__device__ float  g_colsq[DD];
__device__ float  g_bnscale[DD];
__device__ float  g_bnshift[DD];
__device__ int    g_outdeg[NN];
__device__ int    g_indeg[NN];
__device__ float  g_nsrc[NN];
__device__ float  g_ndst[NN];
__device__ int    g_rowptr[NN + 1];
__device__ int    g_cursor[NN];
__device__ int    g_csrsrc[NE];
__device__ int    g_bsums[128];
__device__ __align__(16) __nv_bfloat16 g_Whi[3][16384];
__device__ __align__(16) __nv_bfloat16 g_Wlo[3][16384];

// ======================= graph-side kernels =================================
__global__ void init_graph_k() {
    int i = blockIdx.x * blockDim.x + threadIdx.x;
    if (i < NN) { g_outdeg[i] = 0; g_indeg[i] = 0; }
}

__global__ void degree_k(const int* __restrict__ src, const int* __restrict__ dst) {
    int i = blockIdx.x * blockDim.x + threadIdx.x;
    if (i < NE) {
        atomicAdd(&g_outdeg[src[i]], 1);
        atomicAdd(&g_indeg[dst[i]], 1);
    }
}

// scan over indeg (exclusive per block) + fused norm computation
__global__ void scanA_k() {
    __shared__ int sdata[1024];
    int t = threadIdx.x;
    int i = blockIdx.x * 1024 + t;
    int x = (i < NN) ? g_indeg[i] : 0;
    if (i < NN) {
        g_nsrc[i] = rsqrtf((float)max(g_outdeg[i], 1));
        g_ndst[i] = rsqrtf((float)max(x, 1));
    }
    sdata[t] = x;
    __syncthreads();
    for (int off = 1; off < 1024; off <<= 1) {
        int v = (t >= off) ? sdata[t - off] : 0;
        __syncthreads();
        sdata[t] += v;
        __syncthreads();
    }
    if (i < NN) g_rowptr[i] = sdata[t] - x;
    if (t == 1023) g_bsums[blockIdx.x] = sdata[1023];
}

// parallel exclusive scan of block sums (<=128 entries)
__global__ void scanB_k(int nblocks) {
    __shared__ int s[128];
    int t = threadIdx.x;
    int v = (t < nblocks) ? g_bsums[t] : 0;
    s[t] = v;
    __syncthreads();
    for (int off = 1; off < 128; off <<= 1) {
        int u = (t >= off) ? s[t - off] : 0;
        __syncthreads();
        s[t] += u;
        __syncthreads();
    }
    if (t < nblocks) g_bsums[t] = s[t] - v;
}

__global__ void scanC_k() {
    int i = blockIdx.x * blockDim.x + threadIdx.x;
    if (i < NN) {
        int v = g_rowptr[i] + g_bsums[i >> 10];
        g_rowptr[i] = v;
        g_cursor[i] = v;
    }
    if (i == 0) g_rowptr[NN] = NE;
}

__global__ void csrfill_k(const int* __restrict__ src, const int* __restrict__ dst) {
    int i = blockIdx.x * blockDim.x + threadIdx.x;
    if (i < NE) {
        int pos = atomicAdd(&g_cursor[dst[i]], 1);
        g_csrsrc[pos] = src[i];
    }
}

// ======================= MLP-side small kernels =============================
__global__ void init_mlp_k() {
    int i = threadIdx.x;
    if (i < DD) { g_colsum[i] = 0.f; g_colsq[i] = 0.f; }
}

__global__ void prep_w_all(const float* __restrict__ W1, const float* __restrict__ W2,
                           const float* __restrict__ Wc) {
    int slot = blockIdx.x >> 6;
    const float* W = (slot == 0) ? W1 : (slot == 1) ? W2 : Wc;
    int idx = (blockIdx.x & 63) * 256 + threadIdx.x;
    int n = idx >> 7, k = idx & 127;
    float w = W[k * DD + n];
    __nv_bfloat16 hi = __float2bfloat16(w);
    float r = w - __bfloat162float(hi);
    __nv_bfloat16 lo = __float2bfloat16(r);
    uint32_t o = sw_off(n, k) >> 1;
    g_Whi[slot][o] = hi;
    g_Wlo[slot][o] = lo;
}

__global__ void colstats_k() {
    __shared__ float rs[8][DD];
    __shared__ float rq[8][DD];
    int tid = threadIdx.x;
    int c4 = tid & 31;
    int g = tid >> 5;
    float4 s = make_float4(0.f, 0.f, 0.f, 0.f);
    float4 q = make_float4(0.f, 0.f, 0.f, 0.f);
    const float4* A4 = (const float4*)g_bufA;
    for (int r = blockIdx.x * 8 + g; r < NN; r += gridDim.x * 8) {
        float4 v = A4[(size_t)r * 32 + c4];
        s.x += v.x; s.y += v.y; s.z += v.z; s.w += v.w;
        q.x += v.x * v.x; q.y += v.y * v.y; q.z += v.z * v.z; q.w += v.w * v.w;
    }
    rs[g][c4 * 4 + 0] = s.x; rs[g][c4 * 4 + 1] = s.y; rs[g][c4 * 4 + 2] = s.z; rs[g][c4 * 4 + 3] = s.w;
    rq[g][c4 * 4 + 0] = q.x; rq[g][c4 * 4 + 1] = q.y; rq[g][c4 * 4 + 2] = q.z; rq[g][c4 * 4 + 3] = q.w;
    __syncthreads();
    if (tid < DD) {
        float ss = 0.f, qq = 0.f;
#pragma unroll
        for (int w = 0; w < 8; w++) { ss += rs[w][tid]; qq += rq[w][tid]; }
        atomicAdd(&g_colsum[tid], ss);
        atomicAdd(&g_colsq[tid], qq);
    }
}

__global__ void bn_finalize_k(const float* __restrict__ gamma, const float* __restrict__ beta) {
    int c = threadIdx.x;
    if (c < DD) {
        float inv_n = 1.f / (float)NN;
        float mean = g_colsum[c] * inv_n;
        float var = g_colsq[c] * inv_n - mean * mean;
        float rs = rsqrtf(var + 1e-5f);
        float gsc = gamma[c] * rs;
        g_bnscale[c] = gsc;
        g_bnshift[c] = beta[c] - mean * gsc;
    }
}

// ======================= tensor-core GEMM ===================================
// C[tile 128, 128] = f(A) @ W, split bf16: AhiBhi + AhiBlo + AloBhi, fp32 acc.
// ALOAD: 0 plain, 1 BN+ReLU.  EPI: 0 v=acc+bias, 1 v=acc*ndst+bias.
// OUT: 0 fp32 store to C, 1 fp16 msg store = relu(v)*nsrc.
#define SM_BIAS  0
#define SM_AHI   1024
#define SM_ALO   33792
#define SM_BHI   66560
#define SM_BLO   99328
#define SM_TOTAL 132096

template <int ALOAD, int EPI, int OUT>
__global__ void __launch_bounds__(256, 1)
gemm_mma(const float* __restrict__ Aext, int selA,
         int wslot,
         const float* __restrict__ bias,
         float* __restrict__ Cext, int selC)
{
    extern __shared__ char smem[];
    uint32_t sb = smem_to_u32(smem);
    int tid = threadIdx.x;
    int lane = tid & 31;
    int wid = tid >> 5;
    int rowBase = blockIdx.x * 128;

    const float* A = (selA == 0) ? g_bufA : Aext;
    float*       C = (selC == 0) ? g_bufA : Cext;

    if (tid < 32) ((float4*)(smem + SM_BIAS))[tid] = ((const float4*)bias)[tid];

    // B images: straight copy (2 x 32 KB)
    {
        const uint4* bh = (const uint4*)g_Whi[wslot];
        const uint4* bl = (const uint4*)g_Wlo[wslot];
        uint4* sh = (uint4*)(smem + SM_BHI);
        uint4* sl = (uint4*)(smem + SM_BLO);
#pragma unroll
        for (int i = 0; i < 8; i++) {
            sh[tid + i * 256] = bh[tid + i * 256];
            sl[tid + i * 256] = bl[tid + i * 256];
        }
    }

    // A tile: fp32 load, optional BN+ReLU, split bf16 hi/lo, swizzled smem store
#pragma unroll
    for (int i = 0; i < 16; i++) {
        int t = tid + i * 256;
        int r = t >> 5, q = t & 31;
        int gr = rowBase + r;
        float4 v = make_float4(0.f, 0.f, 0.f, 0.f);
        if (gr < NN) v = ((const float4*)A)[(size_t)gr * 32 + q];
        if (ALOAD == 1) {
            float4 sc = ((const float4*)g_bnscale)[q];
            float4 sh = ((const float4*)g_bnshift)[q];
            v.x = fmaxf(fmaf(v.x, sc.x, sh.x), 0.f);
            v.y = fmaxf(fmaf(v.y, sc.y, sh.y), 0.f);
            v.z = fmaxf(fmaf(v.z, sc.z, sh.z), 0.f);
            v.w = fmaxf(fmaf(v.w, sc.w, sh.w), 0.f);
        }
        __nv_bfloat162 h01 = __floats2bfloat162_rn(v.x, v.y);
        __nv_bfloat162 h23 = __floats2bfloat162_rn(v.z, v.w);
        float lx = v.x - __bfloat162float(__low2bfloat16(h01));
        float ly = v.y - __bfloat162float(__high2bfloat16(h01));
        float lz = v.z - __bfloat162float(__low2bfloat16(h23));
        float lw = v.w - __bfloat162float(__high2bfloat16(h23));
        __nv_bfloat162 l01 = __floats2bfloat162_rn(lx, ly);
        __nv_bfloat162 l23 = __floats2bfloat162_rn(lz, lw);
        uint32_t off = sw_off(r, q * 4);
        asm volatile("st.shared.v2.b32 [%0], {%1, %2};" :: "r"(sb + SM_AHI + off),
                     "r"(*(uint32_t*)&h01), "r"(*(uint32_t*)&h23) : "memory");
        asm volatile("st.shared.v2.b32 [%0], {%1, %2};" :: "r"(sb + SM_ALO + off),
                     "r"(*(uint32_t*)&l01), "r"(*(uint32_t*)&l23) : "memory");
    }
    __syncthreads();

    // A fragments (hi and lo) cached for all 8 K-steps
    uint32_t ah[8][4], al[8][4];
    {
        int ar = wid * 16 + (lane & 15);
        int akh = lane >> 4;
#pragma unroll
        for (int ks = 0; ks < 8; ks++) {
            int c2 = ks * 2 + akh;
            int sw = (c2 & 8) | ((c2 ^ ar) & 7);
            uint32_t aoff = (uint32_t)(ar * 256 + (sw << 4));
            ldsm_x4(ah[ks][0], ah[ks][1], ah[ks][2], ah[ks][3], sb + SM_AHI + aoff);
            ldsm_x4(al[ks][0], al[ks][1], al[ks][2], al[ks][3], sb + SM_ALO + aoff);
        }
    }

    float acc[16][4];
#pragma unroll
    for (int nb = 0; nb < 16; nb++)
#pragma unroll
        for (int j = 0; j < 4; j++) acc[nb][j] = 0.f;

    int bn = lane & 7;
    int bkh = (lane >> 3) & 1;
    uint32_t bRegion = sb + ((lane >> 4) ? SM_BLO : SM_BHI);

#pragma unroll
    for (int nbp = 0; nbp < 8; nbp++) {
        int nb0 = nbp * 2, nb1 = nbp * 2 + 1;
        int brow0 = nb0 * 8 + bn;
        int brow1 = nb1 * 8 + bn;
        uint32_t bf0[8][4], bf1[8][4];
#pragma unroll
        for (int ks = 0; ks < 8; ks++) {
            int c2 = ks * 2 + bkh;
            int sw0 = (c2 & 8) | ((c2 ^ brow0) & 7);
            int sw1 = (c2 & 8) | ((c2 ^ brow1) & 7);
            ldsm_x4(bf0[ks][0], bf0[ks][1], bf0[ks][2], bf0[ks][3],
                    bRegion + brow0 * 256 + (sw0 << 4));
            ldsm_x4(bf1[ks][0], bf1[ks][1], bf1[ks][2], bf1[ks][3],
                    bRegion + brow1 * 256 + (sw1 << 4));
        }
#pragma unroll
        for (int ks = 0; ks < 8; ks++) {
            mma16816(acc[nb0], ah[ks][0], ah[ks][1], ah[ks][2], ah[ks][3], bf0[ks][0], bf0[ks][1]);
            mma16816(acc[nb1], ah[ks][0], ah[ks][1], ah[ks][2], ah[ks][3], bf1[ks][0], bf1[ks][1]);
            mma16816(acc[nb0], ah[ks][0], ah[ks][1], ah[ks][2], ah[ks][3], bf0[ks][2], bf0[ks][3]);
            mma16816(acc[nb1], ah[ks][0], ah[ks][1], ah[ks][2], ah[ks][3], bf1[ks][2], bf1[ks][3]);
            mma16816(acc[nb0], al[ks][0], al[ks][1], al[ks][2], al[ks][3], bf0[ks][0], bf0[ks][1]);
            mma16816(acc[nb1], al[ks][0], al[ks][1], al[ks][2], al[ks][3], bf1[ks][0], bf1[ks][1]);
        }
    }

    // epilogue
    int r0 = rowBase + wid * 16 + (lane >> 2);
    int r1 = r0 + 8;
    float nd0 = 1.f, nd1 = 1.f;
    if (EPI == 1) {
        if (r0 < NN) nd0 = g_ndst[r0];
        if (r1 < NN) nd1 = g_ndst[r1];
    }
    float ns0 = 1.f, ns1 = 1.f;
    if (OUT == 1) {
        if (r0 < NN) ns0 = g_nsrc[r0];
        if (r1 < NN) ns1 = g_nsrc[r1];
    }
    const float* sbias = (const float*)(smem + SM_BIAS);
#pragma unroll
    for (int nb = 0; nb < 16; nb++) {
        int col = nb * 8 + (lane & 3) * 2;
        float bx = sbias[col], by = sbias[col + 1];
        float2 v0, v1;
        if (EPI == 1) {
            v0.x = fmaf(acc[nb][0], nd0, bx); v0.y = fmaf(acc[nb][1], nd0, by);
            v1.x = fmaf(acc[nb][2], nd1, bx); v1.y = fmaf(acc[nb][3], nd1, by);
        } else {
            v0.x = acc[nb][0] + bx; v0.y = acc[nb][1] + by;
            v1.x = acc[nb][2] + bx; v1.y = acc[nb][3] + by;
        }
        if (OUT == 0) {
            if (r0 < NN) ((float2*)C)[(size_t)r0 * 64 + (col >> 1)] = v0;
            if (r1 < NN) ((float2*)C)[(size_t)r1 * 64 + (col >> 1)] = v1;
        } else {
            __half2 m0 = __floats2half2_rn(fmaxf(v0.x, 0.f) * ns0, fmaxf(v0.y, 0.f) * ns0);
            __half2 m1 = __floats2half2_rn(fmaxf(v1.x, 0.f) * ns1, fmaxf(v1.y, 0.f) * ns1);
            if (r0 < NN) ((__half2*)g_msg)[(size_t)r0 * 64 + (col >> 1)] = m0;
            if (r1 < NN) ((__half2*)g_msg)[(size_t)r1 * 64 + (col >> 1)] = m1;
        }
    }
}

// ======================= pull-side edge gather (fp16 msg) ===================
// agg[v] = sum_{e: dst=v} msg[src(e)]   (msg already relu(h)*nsrc, fp16)
__global__ void gather_k() {
    int node = blockIdx.x * 8 + (threadIdx.x >> 5);
    if (node >= NN) return;
    int lane = threadIdx.x & 31;
    int e = g_rowptr[node];
    int end = g_rowptr[node + 1];
    float4 acc = make_float4(0.f, 0.f, 0.f, 0.f);
    const uint2* m = (const uint2*)g_msg;   // row = 32 x uint2 (4 halves each)
    if (e < end) {
        int s = g_csrsrc[e];
        while (true) {
            e++;
            int sn = (e < end) ? g_csrsrc[e] : 0;      // prefetch next index
            uint2 v = m[(size_t)s * 32 + lane];
            float2 f0 = __half22float2(*(const __half2*)&v.x);
            float2 f1 = __half22float2(*(const __half2*)&v.y);
            acc.x += f0.x; acc.y += f0.y; acc.z += f1.x; acc.w += f1.y;
            if (e >= end) break;
            s = sn;
        }
    }
    ((float4*)g_bufA)[(size_t)node * 32 + lane] = acc;
}

// ======================= launch =============================================
extern "C" void kernel_launch(void* const* d_in, const int* in_sizes, int n_in,
                              void* d_out, int out_size)
{
    const float* in_feat = (const float*)d_in[0];
    const int*   src     = (const int*)d_in[1];
    const int*   dst     = (const int*)d_in[2];
    const float* W1      = (const float*)d_in[3];
    const float* b1      = (const float*)d_in[4];
    const float* gamma   = (const float*)d_in[5];
    const float* beta    = (const float*)d_in[6];
    const float* W2      = (const float*)d_in[7];
    const float* b2      = (const float*)d_in[8];
    const float* Wc      = (const float*)d_in[9];
    const float* bc      = (const float*)d_in[10];
    float* out = (float*)d_out;

    cudaFuncSetAttribute(gemm_mma<0,0,0>, cudaFuncAttributeMaxDynamicSharedMemorySize, SM_TOTAL);
    cudaFuncSetAttribute(gemm_mma<1,0,1>, cudaFuncAttributeMaxDynamicSharedMemorySize, SM_TOTAL);
    cudaFuncSetAttribute(gemm_mma<0,1,1>, cudaFuncAttributeMaxDynamicSharedMemorySize, SM_TOTAL);
    cudaFuncSetAttribute(gemm_mma<0,1,0>, cudaFuncAttributeMaxDynamicSharedMemorySize, SM_TOTAL);

    const int nbTiles = (NN + 127) / 128;       // 782
    const int nbN     = (NN + 255) / 256;
    const int nbE     = (NE + 255) / 256;
    const int nbScan  = (NN + 1023) / 1024;     // 98

    // ---- fork: graph-structure chain on side stream -------------------------
    cudaStream_t s2;
    cudaEvent_t evFork, evJoin;
    cudaStreamCreateWithFlags(&s2, cudaStreamNonBlocking);
    cudaEventCreateWithFlags(&evFork, cudaEventDisableTiming);
    cudaEventCreateWithFlags(&evJoin, cudaEventDisableTiming);

    cudaEventRecord(evFork, 0);
    cudaStreamWaitEvent(s2, evFork, 0);

    init_graph_k<<<nbN, 256, 0, s2>>>();
    degree_k<<<nbE, 256, 0, s2>>>(src, dst);
    scanA_k<<<nbScan, 1024, 0, s2>>>();
    scanB_k<<<1, 128, 0, s2>>>(nbScan);
    scanC_k<<<nbN, 256, 0, s2>>>();
    csrfill_k<<<nbE, 256, 0, s2>>>(src, dst);
    cudaEventRecord(evJoin, s2);

    // ---- main stream: MLP chain --------------------------------------------
    init_mlp_k<<<1, 128>>>();
    prep_w_all<<<192, 256>>>(W1, W2, Wc);
    gemm_mma<0,0,0><<<nbTiles, 256, SM_TOTAL>>>(in_feat, 2, 0, b1, nullptr, 0); // -> g_bufA
    colstats_k<<<625, 256>>>();
    bn_finalize_k<<<1, 128>>>(gamma, beta);
    // gemm2 writes msg = relu(h)*nsrc (fp16); needs nsrc -> after join
    cudaStreamWaitEvent(0, evJoin, 0);
    gemm_mma<1,0,1><<<nbTiles, 256, SM_TOTAL>>>(nullptr, 0, 1, b2, nullptr, 0); // -> g_msg

    // ---- propagation x3 -----------------------------------------------------
    for (int step = 0; step < 3; step++) {
        gather_k<<<NN / 8, 256>>>();                                            // msg -> g_bufA
        if (step < 2)
            gemm_mma<0,1,1><<<nbTiles, 256, SM_TOTAL>>>(nullptr, 0, 2, bc, nullptr, 0); // -> g_msg
        else
            gemm_mma<0,1,0><<<nbTiles, 256, SM_TOTAL>>>(nullptr, 0, 2, bc, out, 2);     // -> d_out
    }

    cudaEventDestroy(evFork);
    cudaEventDestroy(evJoin);
    cudaStreamDestroy(s2);
}